// round 16
// baseline (speedup 1.0000x reference)
#include <cuda_runtime.h>
#include <cuda_fp16.h>
#include <math.h>
#include <stdint.h>

#define S_LEN 4096
#define D_MOD 768
#define N_HEAD 12
#define DH 64
#define N_LAYER 4
#define FF_DIM 3072
#define WIN 256

// ---------------- scratch (device globals; no allocation) ----------------
__device__ float  g_x  [S_LEN * D_MOD];
__device__ __half g_xr [S_LEN * D_MOD];
__device__ __half g_qkvh[3 * S_LEN * D_MOD];     // q|k|v fp16, sectioned [sec][S][768]
__device__ __half g_a  [S_LEN * D_MOD];
__device__ float  g_o  [S_LEN * D_MOD];
__device__ __half g_ff [S_LEN * FF_DIM];
__device__ float  g_pooled[D_MOD];
__device__ float  g_h1[512];
__device__ float  g_h2[256];
__device__ float  g_msum[1];
__device__ __half g_qkvT[N_LAYER * 3 * D_MOD * D_MOD];
__device__ __half g_WoT [N_LAYER * D_MOD * D_MOD];
__device__ __half g_f1T [N_LAYER * D_MOD * FF_DIM];
__device__ __half g_f2T [N_LAYER * FF_DIM * D_MOD];
__device__ float  g_bqkv[N_LAYER * 3 * D_MOD];

__device__ __forceinline__ void mma_f16(float* d, const uint32_t* a, const uint32_t* b) {
    asm volatile(
        "mma.sync.aligned.m16n8k16.row.col.f32.f16.f16.f32 "
        "{%0,%1,%2,%3}, {%4,%5,%6,%7}, {%8,%9}, {%0,%1,%2,%3};\n"
        : "+f"(d[0]), "+f"(d[1]), "+f"(d[2]), "+f"(d[3])
        : "r"(a[0]), "r"(a[1]), "r"(a[2]), "r"(a[3]), "r"(b[0]), "r"(b[1]));
}

#define LDSM_X4(d0, d1, d2, d3, addr) \
    asm volatile("ldmatrix.sync.aligned.m8n8.x4.shared.b16 {%0,%1,%2,%3}, [%4];" \
        : "=r"(d0), "=r"(d1), "=r"(d2), "=r"(d3) : "r"(addr))

__device__ __forceinline__ uint32_t smem_u32(const void* p) {
    uint32_t a;
    asm("{ .reg .u64 t; cvta.to.shared.u64 t, %1; cvt.u32.u64 %0, t; }" : "=r"(a) : "l"(p));
    return a;
}

__device__ __forceinline__ void cp_async16(uint32_t saddr, const void* g) {
    asm volatile("cp.async.cg.shared.global [%0], [%1], 16;" :: "r"(saddr), "l"(g) : "memory");
}
#define CP_COMMIT() asm volatile("cp.async.commit_group;" ::: "memory")
#define CP_WAIT1()  asm volatile("cp.async.wait_group 1;" ::: "memory")
#define CP_WAIT0()  asm volatile("cp.async.wait_group 0;" ::: "memory")

// ---------------- unified weight prep: transpose + fp16 + bias fuse --------
__global__ void prep_kernel(const float* __restrict__ Wq, const float* __restrict__ Wk,
                            const float* __restrict__ Wv, const float* __restrict__ Wo,
                            const float* __restrict__ Wff1, const float* __restrict__ Wff2,
                            const float* __restrict__ bq, const float* __restrict__ bk,
                            const float* __restrict__ bv,
                            __half* __restrict__ qkvT, __half* __restrict__ WoT,
                            __half* __restrict__ f1T, __half* __restrict__ f2T,
                            float* __restrict__ bqkv)
{
    int t = blockIdx.x;
    int tx = threadIdx.x, ty = threadIdx.y;
    if (t >= 27648) {
        int layer = t - 27648;
        int flat = ty * 32 + tx;
        for (int i = flat; i < D_MOD; i += 256) {
            bqkv[layer * 3 * D_MOD + i]             = bq[layer * D_MOD + i];
            bqkv[layer * 3 * D_MOD + D_MOD + i]     = bk[layer * D_MOD + i];
            bqkv[layer * 3 * D_MOD + 2 * D_MOD + i] = bv[layer * D_MOD + i];
        }
        return;
    }
    const float* src; __half* dst; int K, N, k0, n0;
    if (t < 6912) {
        int part = t / 2304, r = t % 2304;
        int layer = r / 576, tile = r % 576;
        K = 768; N = 768;
        src = (part == 0 ? Wq : (part == 1 ? Wk : Wv)) + (size_t)layer * 768 * 768;
        dst = qkvT + (size_t)layer * 3 * 768 * 768 + (size_t)part * 768 * 768;
        k0 = (tile / 24) * 32; n0 = (tile % 24) * 32;
    } else if (t < 9216) {
        int r = t - 6912, layer = r / 576, tile = r % 576;
        K = 768; N = 768;
        src = Wo + (size_t)layer * 768 * 768;
        dst = WoT + (size_t)layer * 768 * 768;
        k0 = (tile / 24) * 32; n0 = (tile % 24) * 32;
    } else if (t < 18432) {
        int r = t - 9216, layer = r / 2304, tile = r % 2304;
        K = 768; N = 3072;
        src = Wff1 + (size_t)layer * 768 * 3072;
        dst = f1T + (size_t)layer * 768 * 3072;
        k0 = (tile / 96) * 32; n0 = (tile % 96) * 32;
    } else {
        int r = t - 18432, layer = r / 2304, tile = r % 2304;
        K = 3072; N = 768;
        src = Wff2 + (size_t)layer * 3072 * 768;
        dst = f2T + (size_t)layer * 3072 * 768;
        k0 = (tile / 24) * 32; n0 = (tile % 24) * 32;
    }
    __shared__ float tl[32][33];
#pragma unroll
    for (int i = 0; i < 32; i += 8)
        tl[ty + i][tx] = src[(size_t)(k0 + ty + i) * N + n0 + tx];
    __syncthreads();
#pragma unroll
    for (int i = 0; i < 32; i += 8)
        dst[(size_t)(n0 + ty + i) * K + k0 + tx] = __float2half_rn(tl[tx][ty + i]);
}

// ------ fp16 mma.sync GEMM: 128x256 CTA tile, 64x64 warp tiles, 3 stages ---
#define PAD_H 72
#define ATILE (128 * PAD_H)
#define BTILE (256 * PAD_H)
#define TGH_STAGES 3
#define TGH_SMEM_BYTES (TGH_STAGES * (ATILE + BTILE) * 2)

__device__ __forceinline__ void tg_copy_h(const __half* __restrict__ Ab,
                                          const __half* __restrict__ Bb,
                                          int K, int k0,
                                          __half* sA, __half* sB, int tid)
{
#pragma unroll
    for (int i = 0; i < 4; i++) {       // A: 128 rows x 8 segs
        int idx = tid + i * 256;
        int row = idx >> 3, seg = idx & 7;
        uint32_t da = (uint32_t)__cvta_generic_to_shared(sA + row * PAD_H + seg * 8);
        cp_async16(da, Ab + (size_t)row * K + k0 + seg * 8);
    }
#pragma unroll
    for (int i = 0; i < 8; i++) {       // B: 256 rows x 8 segs
        int idx = tid + i * 256;
        int row = idx >> 3, seg = idx & 7;
        uint32_t db = (uint32_t)__cvta_generic_to_shared(sB + row * PAD_H + seg * 8);
        cp_async16(db, Bb + (size_t)row * K + k0 + seg * 8);
    }
}

__global__ void __launch_bounds__(256, 1) tgemm_kernel(const __half* __restrict__ A,
                                                       const __half* __restrict__ Bt,
                                                       const float* __restrict__ bias,
                                                       void* __restrict__ Cout,
                                                       int M, int N, int K, int epi)
{
    extern __shared__ __half smh[];
    __half* sA = smh;                         // [3][128][72]
    __half* sB = smh + TGH_STAGES * ATILE;    // [3][256][72]

    const int tid  = threadIdx.x;
    const int wid  = tid >> 5;
    const int lane = tid & 31;
    const int wm   = wid & 1;                 // m offset wm*64
    const int wn   = wid >> 1;                // n offset wn*64
    const int g    = lane >> 2;
    const int cq2  = (lane & 3) * 2;
    const int m0 = blockIdx.y * 128;
    const int n0 = blockIdx.x * 256;
    const int NC = K >> 6;

    const __half* Ab = A  + (size_t)m0 * K;
    const __half* Bb = Bt + (size_t)n0 * K;

    const uint32_t smbase = smem_u32(smh);
    const uint32_t a_off = ((wm * 64 + (lane & 7) + ((lane >> 3) & 1) * 8) * PAD_H
                            + (lane >> 4) * 8) * 2;
    const uint32_t b_off = ((wn * 64 + (lane & 7) + (lane >> 4) * 8) * PAD_H
                            + ((lane >> 3) & 1) * 8) * 2;

    float acc[4][8][4];
#pragma unroll
    for (int i = 0; i < 4; i++)
#pragma unroll
        for (int j = 0; j < 8; j++)
#pragma unroll
            for (int r = 0; r < 4; r++) acc[i][j][r] = 0.f;

    tg_copy_h(Ab, Bb, K, 0,  sA,         sB,         tid); CP_COMMIT();
    tg_copy_h(Ab, Bb, K, 64, sA + ATILE, sB + BTILE, tid); CP_COMMIT();

    int st = 0;
    for (int c = 0; c < NC; c++) {
        if (c + 1 < NC) { CP_WAIT1(); } else { CP_WAIT0(); }
        __syncthreads();
        if (c + 2 < NC) {
            int ns = st + 2; if (ns >= TGH_STAGES) ns -= TGH_STAGES;
            tg_copy_h(Ab, Bb, K, (c + 2) << 6, sA + ns * ATILE, sB + ns * BTILE, tid);
            CP_COMMIT();
        }
        const uint32_t aBase = smbase + st * (ATILE * 2) + a_off;
        const uint32_t bBase = smbase + TGH_STAGES * (ATILE * 2) + st * (BTILE * 2) + b_off;
#pragma unroll
        for (int kk = 0; kk < 4; kk++) {
            uint32_t af[4][4], bf[8][2];
#pragma unroll
            for (int mt = 0; mt < 4; mt++)
                LDSM_X4(af[mt][0], af[mt][1], af[mt][2], af[mt][3],
                        aBase + (mt * 16 * PAD_H + kk * 16) * 2);
#pragma unroll
            for (int ntp = 0; ntp < 4; ntp++)
                LDSM_X4(bf[2 * ntp][0], bf[2 * ntp][1], bf[2 * ntp + 1][0], bf[2 * ntp + 1][1],
                        bBase + (ntp * 16 * PAD_H + kk * 16) * 2);
#pragma unroll
            for (int mt = 0; mt < 4; mt++)
#pragma unroll
                for (int nt = 0; nt < 8; nt++)
                    mma_f16(acc[mt][nt], af[mt], bf[nt]);
        }
        st++; if (st >= TGH_STAGES) st = 0;
    }

    // ---- epilogue (256-wide tile never crosses a 768 section: 768 % 256 == 0)
    const int sec = (epi == 3) ? (n0 / 768) : 0;
    const bool qsc = (epi == 3) && (sec == 0);
    __half* dsec = (__half*)Cout + (size_t)sec * S_LEN * 768;
    const int nb = n0 - sec * 768;
    float* Cf = (float*)Cout;
    __half* Ch = (__half*)Cout;
#pragma unroll
    for (int mt = 0; mt < 4; mt++) {
        int row = m0 + wm * 64 + mt * 16 + g;
#pragma unroll
        for (int nt = 0; nt < 8; nt++) {
            int colw = wn * 64 + nt * 8 + cq2;
            int col = n0 + colw;
            float bb0 = bias[col], bb1 = bias[col + 1];
            float v0 = acc[mt][nt][0] + bb0;
            float v1 = acc[mt][nt][1] + bb1;
            float v2 = acc[mt][nt][2] + bb0;
            float v3 = acc[mt][nt][3] + bb1;
            if (epi == 3) {
                if (qsc) { v0 *= 0.125f; v1 *= 0.125f; v2 *= 0.125f; v3 *= 0.125f; }
                int lcol = nb + colw;
                *(__half2*)(dsec + (size_t)row * 768 + lcol)       = __floats2half2_rn(v0, v1);
                *(__half2*)(dsec + (size_t)(row + 8) * 768 + lcol) = __floats2half2_rn(v2, v3);
            } else if (epi == 2) {
                v0 = 0.5f * v0 * (1.0f + erff(v0 * 0.70710678118654752f));
                v1 = 0.5f * v1 * (1.0f + erff(v1 * 0.70710678118654752f));
                v2 = 0.5f * v2 * (1.0f + erff(v2 * 0.70710678118654752f));
                v3 = 0.5f * v3 * (1.0f + erff(v3 * 0.70710678118654752f));
                *(__half2*)(Ch + (size_t)row * N + col)       = __floats2half2_rn(v0, v1);
                *(__half2*)(Ch + (size_t)(row + 8) * N + col) = __floats2half2_rn(v2, v3);
            } else {
                *(float2*)(Cf + (size_t)row * N + col)       = make_float2(v0, v1);
                *(float2*)(Cf + (size_t)(row + 8) * N + col) = make_float2(v2, v3);
            }
        }
    }
}

// ---------------- embedding ----------------
__global__ void embed_kernel(const int* __restrict__ ids,
                             const float* __restrict__ wemb,
                             const float* __restrict__ pemb,
                             float* __restrict__ X)
{
    int row = blockIdx.x;
    int id  = ids[row];
    const float* wp = wemb + (size_t)id * D_MOD;
    const float* pp = pemb + (size_t)row * D_MOD;
    float* xp = X + (size_t)row * D_MOD;
    for (int d = threadIdx.x; d < D_MOD; d += blockDim.x)
        xp[d] = wp[d] + pp[d];
}

// -------- LayerNorm (optional residual), in-place on X; fp16 copy to XR ----
__global__ void __launch_bounds__(256) ln_kernel(float* __restrict__ X,
                                                 const float* __restrict__ Aadd,
                                                 const float* __restrict__ g,
                                                 const float* __restrict__ b,
                                                 __half* __restrict__ XR)
{
    int row = blockIdx.x;
    int tid = threadIdx.x;
    int lane = tid & 31, wid = tid >> 5;
    __shared__ float red[8];
    float vals[3];
    float s = 0.f;
    const size_t base = (size_t)row * D_MOD;
#pragma unroll
    for (int i = 0; i < 3; i++) {
        int d = tid + i * 256;
        float v = X[base + d];
        if (Aadd) v += Aadd[base + d];
        vals[i] = v;
        s += v;
    }
#pragma unroll
    for (int o = 16; o > 0; o >>= 1) s += __shfl_xor_sync(0xFFFFFFFFu, s, o);
    if (lane == 0) red[wid] = s;
    __syncthreads();
    float tot = red[0] + red[1] + red[2] + red[3] + red[4] + red[5] + red[6] + red[7];
    float mean = tot * (1.0f / D_MOD);
    float ss = 0.f;
#pragma unroll
    for (int i = 0; i < 3; i++) { float dv = vals[i] - mean; ss += dv * dv; }
#pragma unroll
    for (int o = 16; o > 0; o >>= 1) ss += __shfl_xor_sync(0xFFFFFFFFu, ss, o);
    __syncthreads();
    if (lane == 0) red[wid] = ss;
    __syncthreads();
    float tot2 = red[0] + red[1] + red[2] + red[3] + red[4] + red[5] + red[6] + red[7];
    float rstd = rsqrtf(tot2 * (1.0f / D_MOD) + 1e-5f);
#pragma unroll
    for (int i = 0; i < 3; i++) {
        int d = tid + i * 256;
        float outv = (vals[i] - mean) * rstd * g[d] + b[d];
        X[base + d] = outv;
        XR[base + d] = __float2half_rn(outv);
    }
}

// ---------------- tensor-core band flash attention --------------------------
#define APITCH 72
#define VPITCH 74
__global__ void __launch_bounds__(128) fattn_kernel(const __half* __restrict__ QKVh,
                                                    const int* __restrict__ mask,
                                                    __half* __restrict__ O)
{
    const __half* Qh = QKVh;
    const __half* Kh = QKVh + (size_t)S_LEN * D_MOD;
    const __half* Vh = QKVh + 2 * (size_t)S_LEN * D_MOD;

    const int qb = blockIdx.x;
    const int h  = blockIdx.y;
    const int qt0 = qb * 64;
    const int tid = threadIdx.x;
    const int w = tid >> 5, lane = tid & 31;
    const int g = lane >> 2, qd = lane & 3;

    __shared__ __align__(16) __half Qs[64][APITCH];
    __shared__ __align__(16) __half Ks[64][APITCH];
    __shared__ __align__(16) __half Vts[64][VPITCH];   // [d][key]
    __shared__ float mbias[64];

    // stage Q
    {
        int r = tid >> 3, seg = tid & 7;
#pragma unroll
        for (int p = 0; p < 4; p++) {
            int row = p * 16 + r;
            *(uint4*)&Qs[row][seg * 8] =
                *(const uint4*)(Qh + (size_t)(qt0 + row) * D_MOD + h * DH + seg * 8);
        }
    }
    __syncthreads();

    uint32_t qf[4][4];
    {
        int r0 = w * 16 + g;
#pragma unroll
        for (int kk = 0; kk < 4; kk++) {
            qf[kk][0] = *(const uint32_t*)&Qs[r0][kk * 16 + 2 * qd];
            qf[kk][1] = *(const uint32_t*)&Qs[r0 + 8][kk * 16 + 2 * qd];
            qf[kk][2] = *(const uint32_t*)&Qs[r0][kk * 16 + 8 + 2 * qd];
            qf[kk][3] = *(const uint32_t*)&Qs[r0 + 8][kk * 16 + 8 + 2 * qd];
        }
    }

    const uint32_t ks_base = smem_u32(Ks) +
        (((lane & 7) + (lane >> 4) * 8) * APITCH + ((lane >> 3) & 1) * 8) * 2;

    float oacc[8][4];
#pragma unroll
    for (int i = 0; i < 8; i++)
#pragma unroll
        for (int r = 0; r < 4; r++) oacc[i][r] = 0.f;
    float m0 = -1e30f, m1 = -1e30f, l0 = 0.f, l1 = 0.f;
    const int i_lo = w * 16 + g, i_hi = i_lo + 8;

    for (int t = 0; t < 9; t++) {
        const int kt0 = qt0 + (t - 4) * 64;
        if (kt0 < 0 || kt0 >= S_LEN) continue;
        __syncthreads();
        {
            int r = tid >> 3, seg = tid & 7;
            bool odd = (r & 1) != 0;
#pragma unroll
            for (int p = 0; p < 4; p++) {
                int row = p * 16 + r;
                *(uint4*)&Ks[row][seg * 8] =
                    *(const uint4*)(Kh + (size_t)(kt0 + row) * D_MOD + h * DH + seg * 8);
                uint4 vv = *(const uint4*)(Vh + (size_t)(kt0 + row) * D_MOD + h * DH + seg * 8);
                uint32_t ox = __shfl_xor_sync(0xFFFFFFFFu, vv.x, 8);
                uint32_t oy = __shfl_xor_sync(0xFFFFFFFFu, vv.y, 8);
                uint32_t oz = __shfl_xor_sync(0xFFFFFFFFu, vv.z, 8);
                uint32_t ow = __shfl_xor_sync(0xFFFFFFFFu, vv.w, 8);
                int prow = row & ~1;
                int dbase = seg * 8 + (odd ? 4 : 0);
                uint32_t a0 = odd ? oz : vv.x;
                uint32_t a1 = odd ? ow : vv.y;
                uint32_t b0 = odd ? vv.z : ox;
                uint32_t b1 = odd ? vv.w : oy;
                *(uint32_t*)&Vts[dbase + 0][prow] = __byte_perm(a0, b0, 0x5410);
                *(uint32_t*)&Vts[dbase + 1][prow] = __byte_perm(a0, b0, 0x7632);
                *(uint32_t*)&Vts[dbase + 2][prow] = __byte_perm(a1, b1, 0x5410);
                *(uint32_t*)&Vts[dbase + 3][prow] = __byte_perm(a1, b1, 0x7632);
            }
        }
        if (tid < 64) mbias[tid] = mask[kt0 + tid] ? 0.f : -1e30f;
        __syncthreads();

        float sf[8][4];
#pragma unroll
        for (int nt = 0; nt < 8; nt++)
            sf[nt][0] = sf[nt][1] = sf[nt][2] = sf[nt][3] = 0.f;
#pragma unroll
        for (int kk = 0; kk < 4; kk++) {
            uint32_t kf[8][2];
#pragma unroll
            for (int ntp = 0; ntp < 4; ntp++)
                LDSM_X4(kf[2 * ntp][0], kf[2 * ntp][1], kf[2 * ntp + 1][0], kf[2 * ntp + 1][1],
                        ks_base + (ntp * 16 * APITCH + kk * 16) * 2);
#pragma unroll
            for (int nt = 0; nt < 8; nt++)
                mma_f16(sf[nt], qf[kk], kf[nt]);
        }
#pragma unroll
        for (int nt = 0; nt < 8; nt++) {
            int j0 = nt * 8 + 2 * qd;
            float mb0 = mbias[j0], mb1 = mbias[j0 + 1];
            sf[nt][0] += mb0; sf[nt][1] += mb1; sf[nt][2] += mb0; sf[nt][3] += mb1;
            if (t == 0) {
                if (j0     < i_lo) sf[nt][0] = -1e30f;
                if (j0 + 1 < i_lo) sf[nt][1] = -1e30f;
                if (j0     < i_hi) sf[nt][2] = -1e30f;
                if (j0 + 1 < i_hi) sf[nt][3] = -1e30f;
            } else if (t == 8) {
                if (j0     > i_lo) sf[nt][0] = -1e30f;
                if (j0 + 1 > i_lo) sf[nt][1] = -1e30f;
                if (j0     > i_hi) sf[nt][2] = -1e30f;
                if (j0 + 1 > i_hi) sf[nt][3] = -1e30f;
            }
        }

        float rm0 = -1e30f, rm1 = -1e30f;
#pragma unroll
        for (int nt = 0; nt < 8; nt++) {
            rm0 = fmaxf(rm0, fmaxf(sf[nt][0], sf[nt][1]));
            rm1 = fmaxf(rm1, fmaxf(sf[nt][2], sf[nt][3]));
        }
        rm0 = fmaxf(rm0, __shfl_xor_sync(0xFFFFFFFFu, rm0, 1));
        rm0 = fmaxf(rm0, __shfl_xor_sync(0xFFFFFFFFu, rm0, 2));
        rm1 = fmaxf(rm1, __shfl_xor_sync(0xFFFFFFFFu, rm1, 1));
        rm1 = fmaxf(rm1, __shfl_xor_sync(0xFFFFFFFFu, rm1, 2));
        float nm0 = fmaxf(m0, rm0), nm1 = fmaxf(m1, rm1);
        float sc0 = __expf(m0 - nm0), sc1 = __expf(m1 - nm1);

        uint32_t pf[4][4];
        float rs0 = 0.f, rs1 = 0.f;
#pragma unroll
        for (int nt = 0; nt < 8; nt++) {
            float e0 = __expf(sf[nt][0] - nm0);
            float e1 = __expf(sf[nt][1] - nm0);
            float e2 = __expf(sf[nt][2] - nm1);
            float e3 = __expf(sf[nt][3] - nm1);
            rs0 += e0 + e1; rs1 += e2 + e3;
            __half2 p01 = __floats2half2_rn(e0, e1);
            __half2 p23 = __floats2half2_rn(e2, e3);
            pf[nt >> 1][(nt & 1) * 2 + 0] = *(uint32_t*)&p01;
            pf[nt >> 1][(nt & 1) * 2 + 1] = *(uint32_t*)&p23;
        }
        rs0 += __shfl_xor_sync(0xFFFFFFFFu, rs0, 1);
        rs0 += __shfl_xor_sync(0xFFFFFFFFu, rs0, 2);
        rs1 += __shfl_xor_sync(0xFFFFFFFFu, rs1, 1);
        rs1 += __shfl_xor_sync(0xFFFFFFFFu, rs1, 2);
        l0 = l0 * sc0 + rs0;
        l1 = l1 * sc1 + rs1;
        m0 = nm0; m1 = nm1;
#pragma unroll
        for (int ntd = 0; ntd < 8; ntd++) {
            oacc[ntd][0] *= sc0; oacc[ntd][1] *= sc0;
            oacc[ntd][2] *= sc1; oacc[ntd][3] *= sc1;
        }
#pragma unroll
        for (int ntd = 0; ntd < 8; ntd++) {
#pragma unroll
            for (int kk = 0; kk < 4; kk++) {
                uint32_t bf[2];
                bf[0] = *(const uint32_t*)&Vts[ntd * 8 + g][kk * 16 + 2 * qd];
                bf[1] = *(const uint32_t*)&Vts[ntd * 8 + g][kk * 16 + 8 + 2 * qd];
                mma_f16(oacc[ntd], pf[kk], bf);
            }
        }
    }

    float inv0 = 1.f / l0, inv1 = 1.f / l1;
    int row0 = qt0 + i_lo;
#pragma unroll
    for (int ntd = 0; ntd < 8; ntd++) {
        int col = h * DH + ntd * 8 + 2 * qd;
        __half2 o0 = __floats2half2_rn(oacc[ntd][0] * inv0, oacc[ntd][1] * inv0);
        __half2 o1 = __floats2half2_rn(oacc[ntd][2] * inv1, oacc[ntd][3] * inv1);
        *(__half2*)(O + (size_t)row0 * D_MOD + col)       = o0;
        *(__half2*)(O + (size_t)(row0 + 8) * D_MOD + col) = o1;
    }
}

// ---------------- pooling + head ----------------
__global__ void zero_pooled_kernel(float* __restrict__ pooled)
{
    for (int d = threadIdx.x; d < D_MOD; d += blockDim.x) pooled[d] = 0.f;
}

__global__ void msum_kernel(const int* __restrict__ mask, float* __restrict__ out)
{
    __shared__ float red[256];
    int tid = threadIdx.x;
    float s = 0.f;
    for (int i = tid; i < S_LEN; i += 256) s += (float)mask[i];
    red[tid] = s; __syncthreads();
    for (int o = 128; o > 0; o >>= 1) { if (tid < o) red[tid] += red[tid + o]; __syncthreads(); }
    if (tid == 0) out[0] = fmaxf(red[0], 1e-9f);
}

__global__ void __launch_bounds__(256) pool_kernel(const float* __restrict__ X,
                                                   const int* __restrict__ mask,
                                                   float* __restrict__ pooled)
{
    int s0 = blockIdx.x * 256;
    int tid = threadIdx.x;
    float a0 = 0.f, a1 = 0.f, a2 = 0.f;
    for (int r = 0; r < 256; r++) {
        float mf = (float)mask[s0 + r];
        const float* xp = X + (size_t)(s0 + r) * D_MOD;
        a0 += xp[tid]       * mf;
        a1 += xp[tid + 256] * mf;
        a2 += xp[tid + 512] * mf;
    }
    atomicAdd(&pooled[tid],       a0);
    atomicAdd(&pooled[tid + 256], a1);
    atomicAdd(&pooled[tid + 512], a2);
}

__global__ void head1_kernel(const float* __restrict__ pooled,
                             const float* __restrict__ W1, const float* __restrict__ b1,
                             const float* __restrict__ msum, float* __restrict__ h1)
{
    int i = threadIdx.x;
    float inv = 1.0f / msum[0];
    float dot = 0.f;
    for (int d = 0; d < D_MOD; d++) dot += pooled[d] * W1[(size_t)d * 512 + i];
    h1[i] = fmaxf(dot * inv + b1[i], 0.f);
}

__global__ void head2_kernel(const float* __restrict__ h1,
                             const float* __restrict__ W2, const float* __restrict__ b2,
                             float* __restrict__ h2)
{
    int i = threadIdx.x;
    if (i < 250) {
        float dot = 0.f;
        for (int d = 0; d < 512; d++) dot += h1[d] * W2[(size_t)d * 250 + i];
        h2[i] = fmaxf(dot + b2[i], 0.f);
    } else if (i < 256) {
        h2[i] = 0.f;
    }
}

__global__ void head3_kernel(const float* __restrict__ h2,
                             const float* __restrict__ W3, const float* __restrict__ b3,
                             float* __restrict__ out, int out_size)
{
    __shared__ float red[256];
    __shared__ float pred;
    int tid = threadIdx.x;
    float v = (tid < 250) ? h2[tid] * W3[tid] : 0.f;
    red[tid] = v; __syncthreads();
    for (int o = 128; o > 0; o >>= 1) { if (tid < o) red[tid] += red[tid + o]; __syncthreads(); }
    if (tid == 0) pred = red[0] + b3[0];
    __syncthreads();
    for (int i = tid; i < out_size; i += 256) out[i] = pred;
}

// ---------------- launch ----------------
extern "C" void kernel_launch(void* const* d_in, const int* in_sizes, int n_in,
                              void* d_out, int out_size)
{
    const int*   ids    = (const int*)  d_in[0];
    const int*   mask   = (const int*)  d_in[1];
    const float* wemb   = (const float*)d_in[2];
    const float* pemb   = (const float*)d_in[3];
    const float* emb_g  = (const float*)d_in[4];
    const float* emb_b  = (const float*)d_in[5];
    const float* Wq     = (const float*)d_in[6];
    const float* Wk     = (const float*)d_in[7];
    const float* Wv     = (const float*)d_in[8];
    const float* Wo     = (const float*)d_in[9];
    const float* bq     = (const float*)d_in[10];
    const float* bk     = (const float*)d_in[11];
    const float* bv     = (const float*)d_in[12];
    const float* bo     = (const float*)d_in[13];
    const float* ln1_g  = (const float*)d_in[14];
    const float* ln1_b  = (const float*)d_in[15];
    const float* Wff1   = (const float*)d_in[16];
    const float* bff1   = (const float*)d_in[17];
    const float* Wff2   = (const float*)d_in[18];
    const float* bff2   = (const float*)d_in[19];
    const float* ln2_g  = (const float*)d_in[20];
    const float* ln2_b  = (const float*)d_in[21];
    const float* W1     = (const float*)d_in[22];
    const float* b1     = (const float*)d_in[23];
    const float* W2     = (const float*)d_in[24];
    const float* b2     = (const float*)d_in[25];
    const float* W3     = (const float*)d_in[26];
    const float* b3     = (const float*)d_in[27];
    float* out = (float*)d_out;

    float *x, *o, *pooled, *h1, *h2, *msum, *bqkv;
    __half *xr, *qkvh, *a, *ff, *qkvT, *WoT, *f1T, *f2T;
    cudaGetSymbolAddress((void**)&x,      g_x);
    cudaGetSymbolAddress((void**)&xr,     g_xr);
    cudaGetSymbolAddress((void**)&qkvh,   g_qkvh);
    cudaGetSymbolAddress((void**)&a,      g_a);
    cudaGetSymbolAddress((void**)&o,      g_o);
    cudaGetSymbolAddress((void**)&ff,     g_ff);
    cudaGetSymbolAddress((void**)&pooled, g_pooled);
    cudaGetSymbolAddress((void**)&h1,     g_h1);
    cudaGetSymbolAddress((void**)&h2,     g_h2);
    cudaGetSymbolAddress((void**)&msum,   g_msum);
    cudaGetSymbolAddress((void**)&qkvT,   g_qkvT);
    cudaGetSymbolAddress((void**)&WoT,    g_WoT);
    cudaGetSymbolAddress((void**)&f1T,    g_f1T);
    cudaGetSymbolAddress((void**)&f2T,    g_f2T);
    cudaGetSymbolAddress((void**)&bqkv,   g_bqkv);

    cudaFuncSetAttribute(tgemm_kernel, cudaFuncAttributeMaxDynamicSharedMemorySize, TGH_SMEM_BYTES);

    dim3 tgQKV(3 * D_MOD / 256, S_LEN / 128);   // (9, 32)
    dim3 tg768 (D_MOD / 256, S_LEN / 128);      // (3, 32)
    dim3 tg3072(FF_DIM / 256, S_LEN / 128);     // (12, 32)

    prep_kernel<<<27652, dim3(32, 8)>>>(Wq, Wk, Wv, Wo, Wff1, Wff2, bq, bk, bv,
                                        qkvT, WoT, f1T, f2T, bqkv);
    embed_kernel<<<S_LEN, 256>>>(ids, wemb, pemb, x);
    ln_kernel<<<S_LEN, 256>>>(x, nullptr, emb_g, emb_b, xr);

    for (int l = 0; l < N_LAYER; l++) {
        const __half* qkvT_l = qkvT + (size_t)l * 3 * D_MOD * D_MOD;
        const __half* WoT_l  = WoT  + (size_t)l * D_MOD * D_MOD;
        const __half* f1T_l  = f1T  + (size_t)l * D_MOD * FF_DIM;
        const __half* f2T_l  = f2T  + (size_t)l * FF_DIM * D_MOD;
        const float*  bqkv_l = bqkv + (size_t)l * 3 * D_MOD;

        tgemm_kernel<<<tgQKV, 256, TGH_SMEM_BYTES>>>(xr, qkvT_l, bqkv_l, qkvh,
                                                     S_LEN, 3 * D_MOD, D_MOD, 3);
        fattn_kernel<<<dim3(S_LEN / 64, N_HEAD), 128>>>(qkvh, mask, a);
        tgemm_kernel<<<tg768, 256, TGH_SMEM_BYTES>>>(a, WoT_l, bo + l * D_MOD, o,
                                                     S_LEN, D_MOD, D_MOD, 0);
        ln_kernel<<<S_LEN, 256>>>(x, o, ln1_g + l * D_MOD, ln1_b + l * D_MOD, xr);

        tgemm_kernel<<<tg3072, 256, TGH_SMEM_BYTES>>>(xr, f1T_l, bff1 + l * FF_DIM, ff,
                                                      S_LEN, FF_DIM, D_MOD, 2);
        tgemm_kernel<<<tg768, 256, TGH_SMEM_BYTES>>>(ff, f2T_l, bff2 + l * D_MOD, o,
                                                     S_LEN, D_MOD, FF_DIM, 0);
        ln_kernel<<<S_LEN, 256>>>(x, o, ln2_g + l * D_MOD, ln2_b + l * D_MOD, xr);
    }

    zero_pooled_kernel<<<1, 256>>>(pooled);
    msum_kernel<<<1, 256>>>(mask, msum);
    pool_kernel<<<S_LEN / 256, 256>>>(x, mask, pooled);
    head1_kernel<<<1, 512>>>(pooled, W1, b1, msum, h1);
    head2_kernel<<<1, 256>>>(h1, W2, b2, h2);
    head3_kernel<<<1, 256>>>(h2, W3, b3, out, out_size);
}

// round 17
// speedup vs baseline: 1.0747x; 1.0747x over previous
#include <cuda_runtime.h>
#include <cuda_fp16.h>
#include <math.h>
#include <stdint.h>

#define S_LEN 4096
#define D_MOD 768
#define N_HEAD 12
#define DH 64
#define N_LAYER 4
#define FF_DIM 3072
#define WIN 256

// ---------------- scratch (device globals; no allocation) ----------------
__device__ float  g_x  [S_LEN * D_MOD];
__device__ __half g_xr [S_LEN * D_MOD];
__device__ __half g_qkvh[3 * S_LEN * D_MOD];     // q|k|v fp16, sectioned [sec][S][768]
__device__ __half g_a  [S_LEN * D_MOD];
__device__ float  g_o  [S_LEN * D_MOD];
__device__ __half g_ff [S_LEN * FF_DIM];
__device__ float  g_pooled[D_MOD];
__device__ float  g_h1[512];
__device__ float  g_h2[256];
__device__ float  g_msum[1];
__device__ __half g_qkvT[N_LAYER * 3 * D_MOD * D_MOD];
__device__ __half g_WoT [N_LAYER * D_MOD * D_MOD];
__device__ __half g_f1T [N_LAYER * D_MOD * FF_DIM];
__device__ __half g_f2T [N_LAYER * FF_DIM * D_MOD];
__device__ float  g_bqkv[N_LAYER * 3 * D_MOD];

__device__ __forceinline__ void mma_f16(float* d, const uint32_t* a, const uint32_t* b) {
    asm volatile(
        "mma.sync.aligned.m16n8k16.row.col.f32.f16.f16.f32 "
        "{%0,%1,%2,%3}, {%4,%5,%6,%7}, {%8,%9}, {%0,%1,%2,%3};\n"
        : "+f"(d[0]), "+f"(d[1]), "+f"(d[2]), "+f"(d[3])
        : "r"(a[0]), "r"(a[1]), "r"(a[2]), "r"(a[3]), "r"(b[0]), "r"(b[1]));
}

#define LDSM_X4(d0, d1, d2, d3, addr) \
    asm volatile("ldmatrix.sync.aligned.m8n8.x4.shared.b16 {%0,%1,%2,%3}, [%4];" \
        : "=r"(d0), "=r"(d1), "=r"(d2), "=r"(d3) : "r"(addr))
#define LDSM_X4_T(d0, d1, d2, d3, addr) \
    asm volatile("ldmatrix.sync.aligned.m8n8.x4.trans.shared.b16 {%0,%1,%2,%3}, [%4];" \
        : "=r"(d0), "=r"(d1), "=r"(d2), "=r"(d3) : "r"(addr))

__device__ __forceinline__ uint32_t smem_u32(const void* p) {
    uint32_t a;
    asm("{ .reg .u64 t; cvta.to.shared.u64 t, %1; cvt.u32.u64 %0, t; }" : "=r"(a) : "l"(p));
    return a;
}

__device__ __forceinline__ void cp_async16(uint32_t saddr, const void* g) {
    asm volatile("cp.async.cg.shared.global [%0], [%1], 16;" :: "r"(saddr), "l"(g) : "memory");
}
#define CP_COMMIT() asm volatile("cp.async.commit_group;" ::: "memory")
#define CP_WAIT1()  asm volatile("cp.async.wait_group 1;" ::: "memory")
#define CP_WAIT0()  asm volatile("cp.async.wait_group 0;" ::: "memory")

// ---------------- unified weight prep: transpose + fp16 + bias fuse --------
__global__ void prep_kernel(const float* __restrict__ Wq, const float* __restrict__ Wk,
                            const float* __restrict__ Wv, const float* __restrict__ Wo,
                            const float* __restrict__ Wff1, const float* __restrict__ Wff2,
                            const float* __restrict__ bq, const float* __restrict__ bk,
                            const float* __restrict__ bv,
                            __half* __restrict__ qkvT, __half* __restrict__ WoT,
                            __half* __restrict__ f1T, __half* __restrict__ f2T,
                            float* __restrict__ bqkv)
{
    int t = blockIdx.x;
    int tx = threadIdx.x, ty = threadIdx.y;
    if (t >= 27648) {
        int layer = t - 27648;
        int flat = ty * 32 + tx;
        for (int i = flat; i < D_MOD; i += 256) {
            bqkv[layer * 3 * D_MOD + i]             = bq[layer * D_MOD + i];
            bqkv[layer * 3 * D_MOD + D_MOD + i]     = bk[layer * D_MOD + i];
            bqkv[layer * 3 * D_MOD + 2 * D_MOD + i] = bv[layer * D_MOD + i];
        }
        return;
    }
    const float* src; __half* dst; int K, N, k0, n0;
    if (t < 6912) {
        int part = t / 2304, r = t % 2304;
        int layer = r / 576, tile = r % 576;
        K = 768; N = 768;
        src = (part == 0 ? Wq : (part == 1 ? Wk : Wv)) + (size_t)layer * 768 * 768;
        dst = qkvT + (size_t)layer * 3 * 768 * 768 + (size_t)part * 768 * 768;
        k0 = (tile / 24) * 32; n0 = (tile % 24) * 32;
    } else if (t < 9216) {
        int r = t - 6912, layer = r / 576, tile = r % 576;
        K = 768; N = 768;
        src = Wo + (size_t)layer * 768 * 768;
        dst = WoT + (size_t)layer * 768 * 768;
        k0 = (tile / 24) * 32; n0 = (tile % 24) * 32;
    } else if (t < 18432) {
        int r = t - 9216, layer = r / 2304, tile = r % 2304;
        K = 768; N = 3072;
        src = Wff1 + (size_t)layer * 768 * 3072;
        dst = f1T + (size_t)layer * 768 * 3072;
        k0 = (tile / 96) * 32; n0 = (tile % 96) * 32;
    } else {
        int r = t - 18432, layer = r / 2304, tile = r % 2304;
        K = 3072; N = 768;
        src = Wff2 + (size_t)layer * 3072 * 768;
        dst = f2T + (size_t)layer * 3072 * 768;
        k0 = (tile / 24) * 32; n0 = (tile % 24) * 32;
    }
    __shared__ float tl[32][33];
#pragma unroll
    for (int i = 0; i < 32; i += 8)
        tl[ty + i][tx] = src[(size_t)(k0 + ty + i) * N + n0 + tx];
    __syncthreads();
#pragma unroll
    for (int i = 0; i < 32; i += 8)
        dst[(size_t)(n0 + ty + i) * K + k0 + tx] = __float2half_rn(tl[tx][ty + i]);
}

// ---------------- fp16 mma.sync GEMM (round-15 config: 128x128, 2 CTA/SM) --
#define PAD_H 72
#define TGH_TILE (128 * PAD_H)
#define TGH_STAGES 3
#define TGH_SMEM_BYTES (TGH_STAGES * 2 * TGH_TILE * 2)

__device__ __forceinline__ void tg_copy_h(const __half* __restrict__ Ab,
                                          const __half* __restrict__ Bb,
                                          int K, int k0,
                                          __half* sA, __half* sB, int tid)
{
#pragma unroll
    for (int i = 0; i < 4; i++) {
        int idx = tid + i * 256;
        int row = idx >> 3, seg = idx & 7;
        uint32_t da = (uint32_t)__cvta_generic_to_shared(sA + row * PAD_H + seg * 8);
        uint32_t db = (uint32_t)__cvta_generic_to_shared(sB + row * PAD_H + seg * 8);
        cp_async16(da, Ab + (size_t)row * K + k0 + seg * 8);
        cp_async16(db, Bb + (size_t)row * K + k0 + seg * 8);
    }
}

__global__ void __launch_bounds__(256, 2) tgemm_kernel(const __half* __restrict__ A,
                                                       const __half* __restrict__ Bt,
                                                       const float* __restrict__ bias,
                                                       void* __restrict__ Cout,
                                                       int M, int N, int K, int epi)
{
    extern __shared__ __half smh[];
    __half* sA = smh;
    __half* sB = smh + TGH_STAGES * TGH_TILE;

    const int tid  = threadIdx.x;
    const int wid  = tid >> 5;
    const int lane = tid & 31;
    const int wm   = wid & 1;
    const int wn   = wid >> 1;
    const int g    = lane >> 2;
    const int cq2  = (lane & 3) * 2;
    const int m0 = blockIdx.y * 128;
    const int n0 = blockIdx.x * 128;
    const int NC = K >> 6;

    const __half* Ab = A  + (size_t)m0 * K;
    const __half* Bb = Bt + (size_t)n0 * K;

    const uint32_t smbase = smem_u32(smh);
    const uint32_t a_off = ((wm * 64 + (lane & 7) + ((lane >> 3) & 1) * 8) * PAD_H
                            + (lane >> 4) * 8) * 2;
    const uint32_t b_off = ((wn * 32 + (lane & 7) + (lane >> 4) * 8) * PAD_H
                            + ((lane >> 3) & 1) * 8) * 2;

    float acc[4][4][4];
#pragma unroll
    for (int i = 0; i < 4; i++)
#pragma unroll
        for (int j = 0; j < 4; j++)
#pragma unroll
            for (int r = 0; r < 4; r++) acc[i][j][r] = 0.f;

    tg_copy_h(Ab, Bb, K, 0,  sA,            sB,            tid); CP_COMMIT();
    tg_copy_h(Ab, Bb, K, 64, sA + TGH_TILE, sB + TGH_TILE, tid); CP_COMMIT();

    int st = 0;
    for (int c = 0; c < NC; c++) {
        if (c + 1 < NC) { CP_WAIT1(); } else { CP_WAIT0(); }
        __syncthreads();
        if (c + 2 < NC) {
            int ns = st + 2; if (ns >= TGH_STAGES) ns -= TGH_STAGES;
            tg_copy_h(Ab, Bb, K, (c + 2) << 6, sA + ns * TGH_TILE, sB + ns * TGH_TILE, tid);
            CP_COMMIT();
        }
        const uint32_t aBase = smbase + st * (TGH_TILE * 2) + a_off;
        const uint32_t bBase = smbase + (TGH_STAGES + st) * (TGH_TILE * 2) + b_off;
#pragma unroll
        for (int kk = 0; kk < 4; kk++) {
            uint32_t af[4][4], bf[4][2];
#pragma unroll
            for (int mt = 0; mt < 4; mt++)
                LDSM_X4(af[mt][0], af[mt][1], af[mt][2], af[mt][3],
                        aBase + (mt * 16 * PAD_H + kk * 16) * 2);
#pragma unroll
            for (int ntp = 0; ntp < 2; ntp++)
                LDSM_X4(bf[2 * ntp][0], bf[2 * ntp][1], bf[2 * ntp + 1][0], bf[2 * ntp + 1][1],
                        bBase + (ntp * 16 * PAD_H + kk * 16) * 2);
#pragma unroll
            for (int mt = 0; mt < 4; mt++)
#pragma unroll
                for (int nt = 0; nt < 4; nt++)
                    mma_f16(acc[mt][nt], af[mt], bf[nt]);
        }
        st++; if (st >= TGH_STAGES) st = 0;
    }

    // ---- epilogue
    const int sec = (epi == 3) ? (n0 / 768) : 0;
    const bool qsc = (epi == 3) && (sec == 0);
    __half* dsec = (__half*)Cout + (size_t)sec * S_LEN * 768;
    const int nb = n0 - sec * 768;
    float* Cf = (float*)Cout;
    __half* Ch = (__half*)Cout;
#pragma unroll
    for (int mt = 0; mt < 4; mt++) {
        int row = m0 + wm * 64 + mt * 16 + g;
#pragma unroll
        for (int nt = 0; nt < 4; nt++) {
            int colw = wn * 32 + nt * 8 + cq2;
            int col = n0 + colw;
            float bb0 = bias[col], bb1 = bias[col + 1];
            float v0 = acc[mt][nt][0] + bb0;
            float v1 = acc[mt][nt][1] + bb1;
            float v2 = acc[mt][nt][2] + bb0;
            float v3 = acc[mt][nt][3] + bb1;
            if (epi == 3) {
                if (qsc) { v0 *= 0.125f; v1 *= 0.125f; v2 *= 0.125f; v3 *= 0.125f; }
                int lcol = nb + colw;
                *(__half2*)(dsec + (size_t)row * 768 + lcol)       = __floats2half2_rn(v0, v1);
                *(__half2*)(dsec + (size_t)(row + 8) * 768 + lcol) = __floats2half2_rn(v2, v3);
            } else if (epi == 2) {
                v0 = 0.5f * v0 * (1.0f + erff(v0 * 0.70710678118654752f));
                v1 = 0.5f * v1 * (1.0f + erff(v1 * 0.70710678118654752f));
                v2 = 0.5f * v2 * (1.0f + erff(v2 * 0.70710678118654752f));
                v3 = 0.5f * v3 * (1.0f + erff(v3 * 0.70710678118654752f));
                *(__half2*)(Ch + (size_t)row * N + col)       = __floats2half2_rn(v0, v1);
                *(__half2*)(Ch + (size_t)(row + 8) * N + col) = __floats2half2_rn(v2, v3);
            } else {
                *(float2*)(Cf + (size_t)row * N + col)       = make_float2(v0, v1);
                *(float2*)(Cf + (size_t)(row + 8) * N + col) = make_float2(v2, v3);
            }
        }
    }
}

// -------- fused embedding + LayerNorm (writes x and fp16 xr) ---------------
__global__ void __launch_bounds__(256) embed_ln_kernel(const int* __restrict__ ids,
                                                       const float* __restrict__ wemb,
                                                       const float* __restrict__ pemb,
                                                       const float* __restrict__ g,
                                                       const float* __restrict__ b,
                                                       float* __restrict__ X,
                                                       __half* __restrict__ XR)
{
    int row = blockIdx.x;
    int tid = threadIdx.x;
    int lane = tid & 31, wid = tid >> 5;
    __shared__ float red[8];
    int id = ids[row];
    const float* wp = wemb + (size_t)id * D_MOD;
    const float* pp = pemb + (size_t)row * D_MOD;
    float vals[3];
    float s = 0.f;
    const size_t base = (size_t)row * D_MOD;
#pragma unroll
    for (int i = 0; i < 3; i++) {
        int d = tid + i * 256;
        float v = wp[d] + pp[d];
        vals[i] = v;
        s += v;
    }
#pragma unroll
    for (int o = 16; o > 0; o >>= 1) s += __shfl_xor_sync(0xFFFFFFFFu, s, o);
    if (lane == 0) red[wid] = s;
    __syncthreads();
    float tot = red[0] + red[1] + red[2] + red[3] + red[4] + red[5] + red[6] + red[7];
    float mean = tot * (1.0f / D_MOD);
    float ss = 0.f;
#pragma unroll
    for (int i = 0; i < 3; i++) { float dv = vals[i] - mean; ss += dv * dv; }
#pragma unroll
    for (int o = 16; o > 0; o >>= 1) ss += __shfl_xor_sync(0xFFFFFFFFu, ss, o);
    __syncthreads();
    if (lane == 0) red[wid] = ss;
    __syncthreads();
    float tot2 = red[0] + red[1] + red[2] + red[3] + red[4] + red[5] + red[6] + red[7];
    float rstd = rsqrtf(tot2 * (1.0f / D_MOD) + 1e-5f);
#pragma unroll
    for (int i = 0; i < 3; i++) {
        int d = tid + i * 256;
        float outv = (vals[i] - mean) * rstd * g[d] + b[d];
        X[base + d] = outv;
        XR[base + d] = __float2half_rn(outv);
    }
}

// -------- LayerNorm (residual add), in-place on X; fp16 copy to XR ---------
__global__ void __launch_bounds__(256) ln_kernel(float* __restrict__ X,
                                                 const float* __restrict__ Aadd,
                                                 const float* __restrict__ g,
                                                 const float* __restrict__ b,
                                                 __half* __restrict__ XR)
{
    int row = blockIdx.x;
    int tid = threadIdx.x;
    int lane = tid & 31, wid = tid >> 5;
    __shared__ float red[8];
    float vals[3];
    float s = 0.f;
    const size_t base = (size_t)row * D_MOD;
#pragma unroll
    for (int i = 0; i < 3; i++) {
        int d = tid + i * 256;
        float v = X[base + d] + Aadd[base + d];
        vals[i] = v;
        s += v;
    }
#pragma unroll
    for (int o = 16; o > 0; o >>= 1) s += __shfl_xor_sync(0xFFFFFFFFu, s, o);
    if (lane == 0) red[wid] = s;
    __syncthreads();
    float tot = red[0] + red[1] + red[2] + red[3] + red[4] + red[5] + red[6] + red[7];
    float mean = tot * (1.0f / D_MOD);
    float ss = 0.f;
#pragma unroll
    for (int i = 0; i < 3; i++) { float dv = vals[i] - mean; ss += dv * dv; }
#pragma unroll
    for (int o = 16; o > 0; o >>= 1) ss += __shfl_xor_sync(0xFFFFFFFFu, ss, o);
    __syncthreads();
    if (lane == 0) red[wid] = ss;
    __syncthreads();
    float tot2 = red[0] + red[1] + red[2] + red[3] + red[4] + red[5] + red[6] + red[7];
    float rstd = rsqrtf(tot2 * (1.0f / D_MOD) + 1e-5f);
#pragma unroll
    for (int i = 0; i < 3; i++) {
        int d = tid + i * 256;
        float outv = (vals[i] - mean) * rstd * g[d] + b[d];
        X[base + d] = outv;
        XR[base + d] = __float2half_rn(outv);
    }
}

// ---------------- tensor-core band flash attention --------------------------
// V staged row-major like K; PV B-fragments come from ldmatrix.x4.trans,
// bit-identical to the previous explicit-transpose path.
#define APITCH 72
__global__ void __launch_bounds__(128) fattn_kernel(const __half* __restrict__ QKVh,
                                                    const int* __restrict__ mask,
                                                    __half* __restrict__ O)
{
    const __half* Qh = QKVh;
    const __half* Kh = QKVh + (size_t)S_LEN * D_MOD;
    const __half* Vh = QKVh + 2 * (size_t)S_LEN * D_MOD;

    const int qb = blockIdx.x;
    const int h  = blockIdx.y;
    const int qt0 = qb * 64;
    const int tid = threadIdx.x;
    const int w = tid >> 5, lane = tid & 31;
    const int g = lane >> 2, qd = lane & 3;

    __shared__ __align__(16) __half Qs[64][APITCH];
    __shared__ __align__(16) __half Ks[64][APITCH];
    __shared__ __align__(16) __half Vs[64][APITCH];   // row-major [key][d]
    __shared__ float mbias[64];

    // stage Q
    {
        int r = tid >> 3, seg = tid & 7;
#pragma unroll
        for (int p = 0; p < 4; p++) {
            int row = p * 16 + r;
            *(uint4*)&Qs[row][seg * 8] =
                *(const uint4*)(Qh + (size_t)(qt0 + row) * D_MOD + h * DH + seg * 8);
        }
    }
    __syncthreads();

    uint32_t qf[4][4];
    {
        int r0 = w * 16 + g;
#pragma unroll
        for (int kk = 0; kk < 4; kk++) {
            qf[kk][0] = *(const uint32_t*)&Qs[r0][kk * 16 + 2 * qd];
            qf[kk][1] = *(const uint32_t*)&Qs[r0 + 8][kk * 16 + 2 * qd];
            qf[kk][2] = *(const uint32_t*)&Qs[r0][kk * 16 + 8 + 2 * qd];
            qf[kk][3] = *(const uint32_t*)&Qs[r0 + 8][kk * 16 + 8 + 2 * qd];
        }
    }

    // ldmatrix lane offsets
    const uint32_t ks_base = smem_u32(Ks) +
        (((lane & 7) + (lane >> 4) * 8) * APITCH + ((lane >> 3) & 1) * 8) * 2;
    // trans variant for V: matrices (j, j+8) x (d, d+8); lane -> row j, col d
    const uint32_t vs_base = smem_u32(Vs) +
        (((lane & 7) + ((lane >> 3) & 1) * 8) * APITCH + (lane >> 4) * 8) * 2;

    float oacc[8][4];
#pragma unroll
    for (int i = 0; i < 8; i++)
#pragma unroll
        for (int r = 0; r < 4; r++) oacc[i][r] = 0.f;
    float m0 = -1e30f, m1 = -1e30f, l0 = 0.f, l1 = 0.f;
    const int i_lo = w * 16 + g, i_hi = i_lo + 8;

    for (int t = 0; t < 9; t++) {
        const int kt0 = qt0 + (t - 4) * 64;
        if (kt0 < 0 || kt0 >= S_LEN) continue;
        __syncthreads();
        {
            int r = tid >> 3, seg = tid & 7;
#pragma unroll
            for (int p = 0; p < 4; p++) {
                int row = p * 16 + r;
                size_t off = (size_t)(kt0 + row) * D_MOD + h * DH + seg * 8;
                *(uint4*)&Ks[row][seg * 8] = *(const uint4*)(Kh + off);
                *(uint4*)&Vs[row][seg * 8] = *(const uint4*)(Vh + off);
            }
        }
        if (tid < 64) mbias[tid] = mask[kt0 + tid] ? 0.f : -1e30f;
        __syncthreads();

        // S = Q K^T
        float sf[8][4];
#pragma unroll
        for (int nt = 0; nt < 8; nt++)
            sf[nt][0] = sf[nt][1] = sf[nt][2] = sf[nt][3] = 0.f;
#pragma unroll
        for (int kk = 0; kk < 4; kk++) {
            uint32_t kf[8][2];
#pragma unroll
            for (int ntp = 0; ntp < 4; ntp++)
                LDSM_X4(kf[2 * ntp][0], kf[2 * ntp][1], kf[2 * ntp + 1][0], kf[2 * ntp + 1][1],
                        ks_base + (ntp * 16 * APITCH + kk * 16) * 2);
#pragma unroll
            for (int nt = 0; nt < 8; nt++)
                mma_f16(sf[nt], qf[kk], kf[nt]);
        }
#pragma unroll
        for (int nt = 0; nt < 8; nt++) {
            int j0 = nt * 8 + 2 * qd;
            float mb0 = mbias[j0], mb1 = mbias[j0 + 1];
            sf[nt][0] += mb0; sf[nt][1] += mb1; sf[nt][2] += mb0; sf[nt][3] += mb1;
            if (t == 0) {
                if (j0     < i_lo) sf[nt][0] = -1e30f;
                if (j0 + 1 < i_lo) sf[nt][1] = -1e30f;
                if (j0     < i_hi) sf[nt][2] = -1e30f;
                if (j0 + 1 < i_hi) sf[nt][3] = -1e30f;
            } else if (t == 8) {
                if (j0     > i_lo) sf[nt][0] = -1e30f;
                if (j0 + 1 > i_lo) sf[nt][1] = -1e30f;
                if (j0     > i_hi) sf[nt][2] = -1e30f;
                if (j0 + 1 > i_hi) sf[nt][3] = -1e30f;
            }
        }

        // online softmax
        float rm0 = -1e30f, rm1 = -1e30f;
#pragma unroll
        for (int nt = 0; nt < 8; nt++) {
            rm0 = fmaxf(rm0, fmaxf(sf[nt][0], sf[nt][1]));
            rm1 = fmaxf(rm1, fmaxf(sf[nt][2], sf[nt][3]));
        }
        rm0 = fmaxf(rm0, __shfl_xor_sync(0xFFFFFFFFu, rm0, 1));
        rm0 = fmaxf(rm0, __shfl_xor_sync(0xFFFFFFFFu, rm0, 2));
        rm1 = fmaxf(rm1, __shfl_xor_sync(0xFFFFFFFFu, rm1, 1));
        rm1 = fmaxf(rm1, __shfl_xor_sync(0xFFFFFFFFu, rm1, 2));
        float nm0 = fmaxf(m0, rm0), nm1 = fmaxf(m1, rm1);
        float sc0 = __expf(m0 - nm0), sc1 = __expf(m1 - nm1);

        uint32_t pf[4][4];
        float rs0 = 0.f, rs1 = 0.f;
#pragma unroll
        for (int nt = 0; nt < 8; nt++) {
            float e0 = __expf(sf[nt][0] - nm0);
            float e1 = __expf(sf[nt][1] - nm0);
            float e2 = __expf(sf[nt][2] - nm1);
            float e3 = __expf(sf[nt][3] - nm1);
            rs0 += e0 + e1; rs1 += e2 + e3;
            __half2 p01 = __floats2half2_rn(e0, e1);
            __half2 p23 = __floats2half2_rn(e2, e3);
            pf[nt >> 1][(nt & 1) * 2 + 0] = *(uint32_t*)&p01;
            pf[nt >> 1][(nt & 1) * 2 + 1] = *(uint32_t*)&p23;
        }
        rs0 += __shfl_xor_sync(0xFFFFFFFFu, rs0, 1);
        rs0 += __shfl_xor_sync(0xFFFFFFFFu, rs0, 2);
        rs1 += __shfl_xor_sync(0xFFFFFFFFu, rs1, 1);
        rs1 += __shfl_xor_sync(0xFFFFFFFFu, rs1, 2);
        l0 = l0 * sc0 + rs0;
        l1 = l1 * sc1 + rs1;
        m0 = nm0; m1 = nm1;
#pragma unroll
        for (int ntd = 0; ntd < 8; ntd++) {
            oacc[ntd][0] *= sc0; oacc[ntd][1] *= sc0;
            oacc[ntd][2] *= sc1; oacc[ntd][3] *= sc1;
        }
        // O += P V : B-frags via ldmatrix.trans on row-major Vs
#pragma unroll
        for (int kk = 0; kk < 4; kk++) {
            uint32_t vf[8][2];
#pragma unroll
            for (int p = 0; p < 4; p++)
                LDSM_X4_T(vf[2 * p][0], vf[2 * p][1], vf[2 * p + 1][0], vf[2 * p + 1][1],
                          vs_base + (kk * 16 * APITCH + p * 16) * 2);
#pragma unroll
            for (int ntd = 0; ntd < 8; ntd++)
                mma_f16(oacc[ntd], pf[kk], vf[ntd]);
        }
    }

    float inv0 = 1.f / l0, inv1 = 1.f / l1;
    int row0 = qt0 + i_lo;
#pragma unroll
    for (int ntd = 0; ntd < 8; ntd++) {
        int col = h * DH + ntd * 8 + 2 * qd;
        __half2 o0 = __floats2half2_rn(oacc[ntd][0] * inv0, oacc[ntd][1] * inv0);
        __half2 o1 = __floats2half2_rn(oacc[ntd][2] * inv1, oacc[ntd][3] * inv1);
        *(__half2*)(O + (size_t)row0 * D_MOD + col)       = o0;
        *(__half2*)(O + (size_t)(row0 + 8) * D_MOD + col) = o1;
    }
}

// ---------------- pooling + head ----------------
__global__ void zero_msum_kernel(const int* __restrict__ mask,
                                 float* __restrict__ pooled, float* __restrict__ out)
{
    __shared__ float red[256];
    int tid = threadIdx.x;
    for (int d = tid; d < D_MOD; d += 256) pooled[d] = 0.f;
    float s = 0.f;
    for (int i = tid; i < S_LEN; i += 256) s += (float)mask[i];
    red[tid] = s; __syncthreads();
    for (int o = 128; o > 0; o >>= 1) { if (tid < o) red[tid] += red[tid + o]; __syncthreads(); }
    if (tid == 0) out[0] = fmaxf(red[0], 1e-9f);
}

__global__ void __launch_bounds__(256) pool_kernel(const float* __restrict__ X,
                                                   const int* __restrict__ mask,
                                                   float* __restrict__ pooled)
{
    int s0 = blockIdx.x * 256;
    int tid = threadIdx.x;
    float a0 = 0.f, a1 = 0.f, a2 = 0.f;
    for (int r = 0; r < 256; r++) {
        float mf = (float)mask[s0 + r];
        const float* xp = X + (size_t)(s0 + r) * D_MOD;
        a0 += xp[tid]       * mf;
        a1 += xp[tid + 256] * mf;
        a2 += xp[tid + 512] * mf;
    }
    atomicAdd(&pooled[tid],       a0);
    atomicAdd(&pooled[tid + 256], a1);
    atomicAdd(&pooled[tid + 512], a2);
}

__global__ void head1_kernel(const float* __restrict__ pooled,
                             const float* __restrict__ W1, const float* __restrict__ b1,
                             const float* __restrict__ msum, float* __restrict__ h1)
{
    int i = threadIdx.x;
    float inv = 1.0f / msum[0];
    float dot = 0.f;
    for (int d = 0; d < D_MOD; d++) dot += pooled[d] * W1[(size_t)d * 512 + i];
    h1[i] = fmaxf(dot * inv + b1[i], 0.f);
}

__global__ void head2_kernel(const float* __restrict__ h1,
                             const float* __restrict__ W2, const float* __restrict__ b2,
                             float* __restrict__ h2)
{
    int i = threadIdx.x;
    if (i < 250) {
        float dot = 0.f;
        for (int d = 0; d < 512; d++) dot += h1[d] * W2[(size_t)d * 250 + i];
        h2[i] = fmaxf(dot + b2[i], 0.f);
    } else if (i < 256) {
        h2[i] = 0.f;
    }
}

__global__ void head3_kernel(const float* __restrict__ h2,
                             const float* __restrict__ W3, const float* __restrict__ b3,
                             float* __restrict__ out, int out_size)
{
    __shared__ float red[256];
    __shared__ float pred;
    int tid = threadIdx.x;
    float v = (tid < 250) ? h2[tid] * W3[tid] : 0.f;
    red[tid] = v; __syncthreads();
    for (int o = 128; o > 0; o >>= 1) { if (tid < o) red[tid] += red[tid + o]; __syncthreads(); }
    if (tid == 0) pred = red[0] + b3[0];
    __syncthreads();
    for (int i = tid; i < out_size; i += 256) out[i] = pred;
}

// ---------------- launch ----------------
extern "C" void kernel_launch(void* const* d_in, const int* in_sizes, int n_in,
                              void* d_out, int out_size)
{
    const int*   ids    = (const int*)  d_in[0];
    const int*   mask   = (const int*)  d_in[1];
    const float* wemb   = (const float*)d_in[2];
    const float* pemb   = (const float*)d_in[3];
    const float* emb_g  = (const float*)d_in[4];
    const float* emb_b  = (const float*)d_in[5];
    const float* Wq     = (const float*)d_in[6];
    const float* Wk     = (const float*)d_in[7];
    const float* Wv     = (const float*)d_in[8];
    const float* Wo     = (const float*)d_in[9];
    const float* bq     = (const float*)d_in[10];
    const float* bk     = (const float*)d_in[11];
    const float* bv     = (const float*)d_in[12];
    const float* bo     = (const float*)d_in[13];
    const float* ln1_g  = (const float*)d_in[14];
    const float* ln1_b  = (const float*)d_in[15];
    const float* Wff1   = (const float*)d_in[16];
    const float* bff1   = (const float*)d_in[17];
    const float* Wff2   = (const float*)d_in[18];
    const float* bff2   = (const float*)d_in[19];
    const float* ln2_g  = (const float*)d_in[20];
    const float* ln2_b  = (const float*)d_in[21];
    const float* W1     = (const float*)d_in[22];
    const float* b1     = (const float*)d_in[23];
    const float* W2     = (const float*)d_in[24];
    const float* b2     = (const float*)d_in[25];
    const float* W3     = (const float*)d_in[26];
    const float* b3     = (const float*)d_in[27];
    float* out = (float*)d_out;

    float *x, *o, *pooled, *h1, *h2, *msum, *bqkv;
    __half *xr, *qkvh, *a, *ff, *qkvT, *WoT, *f1T, *f2T;
    cudaGetSymbolAddress((void**)&x,      g_x);
    cudaGetSymbolAddress((void**)&xr,     g_xr);
    cudaGetSymbolAddress((void**)&qkvh,   g_qkvh);
    cudaGetSymbolAddress((void**)&a,      g_a);
    cudaGetSymbolAddress((void**)&o,      g_o);
    cudaGetSymbolAddress((void**)&ff,     g_ff);
    cudaGetSymbolAddress((void**)&pooled, g_pooled);
    cudaGetSymbolAddress((void**)&h1,     g_h1);
    cudaGetSymbolAddress((void**)&h2,     g_h2);
    cudaGetSymbolAddress((void**)&msum,   g_msum);
    cudaGetSymbolAddress((void**)&qkvT,   g_qkvT);
    cudaGetSymbolAddress((void**)&WoT,    g_WoT);
    cudaGetSymbolAddress((void**)&f1T,    g_f1T);
    cudaGetSymbolAddress((void**)&f2T,    g_f2T);
    cudaGetSymbolAddress((void**)&bqkv,   g_bqkv);

    cudaFuncSetAttribute(tgemm_kernel, cudaFuncAttributeMaxDynamicSharedMemorySize, TGH_SMEM_BYTES);

    dim3 tgQKV(3 * D_MOD / 128, S_LEN / 128);   // (18, 32)
    dim3 tg768 (D_MOD / 128, S_LEN / 128);      // (6, 32)
    dim3 tg3072(FF_DIM / 128, S_LEN / 128);     // (24, 32)

    prep_kernel<<<27652, dim3(32, 8)>>>(Wq, Wk, Wv, Wo, Wff1, Wff2, bq, bk, bv,
                                        qkvT, WoT, f1T, f2T, bqkv);
    embed_ln_kernel<<<S_LEN, 256>>>(ids, wemb, pemb, emb_g, emb_b, x, xr);

    for (int l = 0; l < N_LAYER; l++) {
        const __half* qkvT_l = qkvT + (size_t)l * 3 * D_MOD * D_MOD;
        const __half* WoT_l  = WoT  + (size_t)l * D_MOD * D_MOD;
        const __half* f1T_l  = f1T  + (size_t)l * D_MOD * FF_DIM;
        const __half* f2T_l  = f2T  + (size_t)l * FF_DIM * D_MOD;
        const float*  bqkv_l = bqkv + (size_t)l * 3 * D_MOD;

        tgemm_kernel<<<tgQKV, 256, TGH_SMEM_BYTES>>>(xr, qkvT_l, bqkv_l, qkvh,
                                                     S_LEN, 3 * D_MOD, D_MOD, 3);
        fattn_kernel<<<dim3(S_LEN / 64, N_HEAD), 128>>>(qkvh, mask, a);
        tgemm_kernel<<<tg768, 256, TGH_SMEM_BYTES>>>(a, WoT_l, bo + l * D_MOD, o,
                                                     S_LEN, D_MOD, D_MOD, 0);
        ln_kernel<<<S_LEN, 256>>>(x, o, ln1_g + l * D_MOD, ln1_b + l * D_MOD, xr);

        tgemm_kernel<<<tg3072, 256, TGH_SMEM_BYTES>>>(xr, f1T_l, bff1 + l * FF_DIM, ff,
                                                      S_LEN, FF_DIM, D_MOD, 2);
        tgemm_kernel<<<tg768, 256, TGH_SMEM_BYTES>>>(ff, f2T_l, bff2 + l * D_MOD, o,
                                                     S_LEN, D_MOD, FF_DIM, 0);
        ln_kernel<<<S_LEN, 256>>>(x, o, ln2_g + l * D_MOD, ln2_b + l * D_MOD, xr);
    }

    zero_msum_kernel<<<1, 256>>>(mask, pooled, msum);
    pool_kernel<<<S_LEN / 256, 256>>>(x, mask, pooled);
    head1_kernel<<<1, 512>>>(pooled, W1, b1, msum, h1);
    head2_kernel<<<1, 256>>>(h1, W2, b2, h2);
    head3_kernel<<<1, 256>>>(h2, W3, b3, out, out_size);
}